// round 13
// baseline (speedup 1.0000x reference)
#include <cuda_runtime.h>
#include <cstdint>

#define NN 100000
#define NE 1600000
#define DC 128
#define NL 3
#define NBLK 98          // ceil(NN/1024)

// ---------------- scratch (device globals; no allocations allowed) ----------
// g_stats invariant: zero at entry of every kernel_launch (zero-init at load;
// the last GEMM CTA re-zeroes after consuming). g_cnt likewise returns to 0.
__device__ float g_z [(size_t)NN * DC];
__device__ float g_t1[(size_t)NN * DC];
__device__ float g_t2[(size_t)NN * DC];
__device__ float g_stats[2 * DC];
__device__ float g_aff [2 * DC];
__device__ int   g_cnt;
__device__ int   g_deg[NN];
__device__ int   g_pos[NN];
__device__ int   g_off[NN + 1];
__device__ int   g_csr[NE];
__device__ int   g_bsum[NBLK];

// ---------------- tiny utility kernels --------------------------------------
__global__ void k_zero_deg()
{
    int i = blockIdx.x * blockDim.x + threadIdx.x;
    if (i < NN) g_deg[i] = 0;
}

// final output: out = a*in + c (BN2 of last layer, no ReLU)
__global__ void k_affine(const float* __restrict__ in, float* __restrict__ out)
{
    int i = blockIdx.x * blockDim.x + threadIdx.x;
    const int n4 = NN * DC / 4;
    if (i >= n4) return;
    float4 v = __ldg((const float4*)in + i);
    int c4 = i & (DC / 4 - 1);
    float4 a = *((const float4*)g_aff + c4);
    float4 c = *((const float4*)g_aff + DC / 4 + c4);
    v.x = fmaf(a.x, v.x, c.x);
    v.y = fmaf(a.y, v.y, c.y);
    v.z = fmaf(a.z, v.z, c.z);
    v.w = fmaf(a.w, v.w, c.w);
    ((float4*)out)[i] = v;
}

// ---------------- CSR build ---------------------------------------------------
__global__ void k_hist(const int* __restrict__ ei)
{
    int q = blockIdx.x * blockDim.x + threadIdx.x;
    if (q >= NE / 4) return;
    int4 d = __ldg((const int4*)(ei + NE) + q);
    atomicAdd(&g_deg[d.x], 1);
    atomicAdd(&g_deg[d.y], 1);
    atomicAdd(&g_deg[d.z], 1);
    atomicAdd(&g_deg[d.w], 1);
}

__global__ void k_scan1()
{
    __shared__ int ws[32];
    int t = threadIdx.x;
    int i = blockIdx.x * 1024 + t;
    int v = (i < NN) ? g_deg[i] : 0;
    #pragma unroll
    for (int d = 16; d; d >>= 1) v += __shfl_down_sync(0xFFFFFFFF, v, d);
    if ((t & 31) == 0) ws[t >> 5] = v;
    __syncthreads();
    if (t < 32) {
        int x = ws[t];
        #pragma unroll
        for (int d = 16; d; d >>= 1) x += __shfl_down_sync(0xFFFFFFFF, x, d);
        if (t == 0) g_bsum[blockIdx.x] = x;
    }
}

__global__ void k_scan2()
{
    __shared__ int s[128];
    int t = threadIdx.x;
    s[t] = (t < NBLK) ? g_bsum[t] : 0;
    __syncthreads();
    for (int off = 1; off < 128; off <<= 1) {
        int v = s[t];
        int a = (t >= off) ? s[t - off] : 0;
        __syncthreads();
        s[t] = v + a;
        __syncthreads();
    }
    if (t < NBLK) g_bsum[t] = (t > 0) ? s[t - 1] : 0;
}

__global__ void k_scan3()
{
    __shared__ int ws[32];
    int t = threadIdx.x;
    int lane = t & 31, wid = t >> 5;
    int i = blockIdx.x * 1024 + t;
    int v = (i < NN) ? g_deg[i] : 0;
    int incl = v;
    #pragma unroll
    for (int d = 1; d < 32; d <<= 1) {
        int n = __shfl_up_sync(0xFFFFFFFF, incl, d);
        if (lane >= d) incl += n;
    }
    if (lane == 31) ws[wid] = incl;
    __syncthreads();
    if (wid == 0) {
        int x = ws[lane];
        #pragma unroll
        for (int d = 1; d < 32; d <<= 1) {
            int n = __shfl_up_sync(0xFFFFFFFF, x, d);
            if (lane >= d) x += n;
        }
        ws[lane] = x;
    }
    __syncthreads();
    int excl = incl - v + ((wid > 0) ? ws[wid - 1] : 0) + g_bsum[blockIdx.x];
    if (i < NN) { g_off[i] = excl; g_pos[i] = excl; }
    if (i == 0) g_off[NN] = NE;
}

__global__ void k_fill(const int* __restrict__ ei)
{
    int q = blockIdx.x * blockDim.x + threadIdx.x;
    if (q >= NE / 4) return;
    int4 s = __ldg((const int4*)ei + q);
    int4 d = __ldg((const int4*)(ei + NE) + q);
    g_csr[atomicAdd(&g_pos[d.x], 1)] = s.x;
    g_csr[atomicAdd(&g_pos[d.y], 1)] = s.y;
    g_csr[atomicAdd(&g_pos[d.z], 1)] = s.z;
    g_csr[atomicAdd(&g_pos[d.w], 1)] = s.w;
}

// ---------------- CSR aggregation: z[n] = f(h[n]) + sum_{s in N(n)} f(h[s]) ---
// warp per node, lane covers 4 channels; BN affine(+relu) fused into reads.
template<bool AFF>
__global__ void k_aggr(const float* __restrict__ h, int relu)
{
    int gt = blockIdx.x * blockDim.x + threadIdx.x;
    int n = gt >> 5;
    int lane = gt & 31;
    if (n >= NN) return;

    float4 a, c;
    if (AFF) {
        a = *((const float4*)g_aff + lane);
        c = *((const float4*)g_aff + DC / 4 + lane);
    }

    auto fetch = [&](int s) -> float4 {
        float4 v = __ldg((const float4*)(h + (size_t)s * DC) + lane);
        if (AFF) {
            v.x = fmaf(a.x, v.x, c.x);
            v.y = fmaf(a.y, v.y, c.y);
            v.z = fmaf(a.z, v.z, c.z);
            v.w = fmaf(a.w, v.w, c.w);
            if (relu) {
                v.x = fmaxf(v.x, 0.f); v.y = fmaxf(v.y, 0.f);
                v.z = fmaxf(v.z, 0.f); v.w = fmaxf(v.w, 0.f);
            }
        }
        return v;
    };

    float4 acc = fetch(n);   // self term (eps = 0)

    const int i0 = __ldg(g_off + n);
    const int i1 = __ldg(g_off + n + 1);
    int s_cur = 0, s_nxt = 0;
    if (i0 < i1)     s_cur = __ldg(g_csr + i0);
    if (i0 + 1 < i1) s_nxt = __ldg(g_csr + i0 + 1);
    for (int i = i0; i < i1; i++) {
        int s = s_cur;
        s_cur = s_nxt;
        if (i + 2 < i1) s_nxt = __ldg(g_csr + i + 2);
        float4 v = fetch(s);
        acc.x += v.x; acc.y += v.y; acc.z += v.z; acc.w += v.w;
    }
    *((float4*)(g_z + (size_t)n * DC) + lane) = acc;
}

// ---------------- fp32 FFMA GEMM + bias + BN-stats + fused BN-affine ---------
// out[m][n] = sum_k f(A[m][k]) * W[k][n] + bias[n]; K chunked 2x64.
// 256 thr, 128x128 tile, 8x8 thread tile, 2 CTAs/SM. At the FFMA roofline.
// The LAST finishing CTA (global counter) computes g_aff from g_stats
// (BN gamma/beta -> per-channel affine) and resets stats: replaces k_bn.
#define KCH 64
#define SAP 68   // A pitch (floats)

template<bool AFF>
__global__ void __launch_bounds__(256, 2)
k_gemm(const float* __restrict__ A, const float* __restrict__ W,
       const float* __restrict__ bias, float* __restrict__ out, int nrows,
       const float* __restrict__ gamma, const float* __restrict__ beta)
{
    extern __shared__ float sm[];
    float* sA   = sm;                    // [128][SAP]  (chunk-local k)
    float* sB   = sm + 128 * SAP;        // [KCH][128]
    float* sSum = sB + KCH * 128;        // [128]
    float* sSq  = sSum + DC;             // [128]
    __shared__ int sLast;

    const int t = threadIdx.x;
    const int blockRow = blockIdx.x * 128;

    if (t < DC) { sSum[t] = 0.f; sSq[t] = 0.f; }

    const int tx = t & 15, ty = t >> 4;
    const int m0 = ty * 8, n0 = tx * 8;

    float acc[8][8];
    #pragma unroll
    for (int i = 0; i < 8; i++)
        #pragma unroll
        for (int j = 0; j < 8; j++)
            acc[i][j] = 0.f;

    for (int kc = 0; kc < 2; kc++) {
        // W chunk: rows [kc*64, kc*64+64), all 128 cols
        #pragma unroll
        for (int i = 0; i < 8; i++) {
            int idx = i * 256 + t;          // float4 idx over 64x128
            int kl  = idx >> 5;
            int n4  = idx & 31;
            float4 v = __ldg((const float4*)W + (kc * KCH + kl) * 32 + n4);
            *(float4*)(sB + kl * 128 + n4 * 4) = v;
        }
        // A chunk: 128 rows x 64 cols, fused affine+relu; zero-pad invalid rows
        #pragma unroll
        for (int i = 0; i < 8; i++) {
            int idx = i * 256 + t;          // float4 idx over 128x64
            int m   = idx >> 4;
            int k4  = idx & 15;
            int gm  = blockRow + m;
            float4 v = make_float4(0.f, 0.f, 0.f, 0.f);
            if (gm < nrows) {
                v = __ldg((const float4*)(A + (size_t)gm * DC) + kc * 16 + k4);
                if (AFF) {
                    float4 a = *((const float4*)g_aff + kc * 16 + k4);
                    float4 c = *((const float4*)g_aff + DC / 4 + kc * 16 + k4);
                    v.x = fmaxf(fmaf(a.x, v.x, c.x), 0.f);
                    v.y = fmaxf(fmaf(a.y, v.y, c.y), 0.f);
                    v.z = fmaxf(fmaf(a.z, v.z, c.z), 0.f);
                    v.w = fmaxf(fmaf(a.w, v.w, c.w), 0.f);
                }
            }
            *(float4*)(sA + m * SAP + k4 * 4) = v;
        }
        __syncthreads();

        #pragma unroll 2
        for (int k0 = 0; k0 < KCH; k0 += 4) {
            float4 av[8];
            #pragma unroll
            for (int i = 0; i < 8; i++)
                av[i] = *(const float4*)(sA + (m0 + i) * SAP + k0);
            #pragma unroll
            for (int kk = 0; kk < 4; kk++) {
                float4 b0 = *(const float4*)(sB + (k0 + kk) * 128 + n0);
                float4 b1 = *(const float4*)(sB + (k0 + kk) * 128 + n0 + 4);
                #pragma unroll
                for (int i = 0; i < 8; i++) {
                    float a = (kk == 0) ? av[i].x : (kk == 1) ? av[i].y
                            : (kk == 2) ? av[i].z : av[i].w;
                    acc[i][0] = fmaf(a, b0.x, acc[i][0]);
                    acc[i][1] = fmaf(a, b0.y, acc[i][1]);
                    acc[i][2] = fmaf(a, b0.z, acc[i][2]);
                    acc[i][3] = fmaf(a, b0.w, acc[i][3]);
                    acc[i][4] = fmaf(a, b1.x, acc[i][4]);
                    acc[i][5] = fmaf(a, b1.y, acc[i][5]);
                    acc[i][6] = fmaf(a, b1.z, acc[i][6]);
                    acc[i][7] = fmaf(a, b1.w, acc[i][7]);
                }
            }
        }
        __syncthreads();
    }

    // ---- epilogue: bias, store, per-channel stats ----
    float4 bv0 = __ldg((const float4*)(bias + n0));
    float4 bv1 = __ldg((const float4*)(bias + n0) + 1);
    float csum[8] = {0, 0, 0, 0, 0, 0, 0, 0};
    float csq [8] = {0, 0, 0, 0, 0, 0, 0, 0};
    #pragma unroll
    for (int i = 0; i < 8; i++) {
        int gm = blockRow + m0 + i;
        float v0 = acc[i][0] + bv0.x, v1 = acc[i][1] + bv0.y;
        float v2 = acc[i][2] + bv0.z, v3 = acc[i][3] + bv0.w;
        float v4 = acc[i][4] + bv1.x, v5 = acc[i][5] + bv1.y;
        float v6 = acc[i][6] + bv1.z, v7 = acc[i][7] + bv1.w;
        if (gm < nrows) {
            float* po = out + (size_t)gm * DC + n0;
            *(float4*)po       = make_float4(v0, v1, v2, v3);
            *(float4*)(po + 4) = make_float4(v4, v5, v6, v7);
            csum[0] += v0; csq[0] += v0 * v0;
            csum[1] += v1; csq[1] += v1 * v1;
            csum[2] += v2; csq[2] += v2 * v2;
            csum[3] += v3; csq[3] += v3 * v3;
            csum[4] += v4; csq[4] += v4 * v4;
            csum[5] += v5; csq[5] += v5 * v5;
            csum[6] += v6; csq[6] += v6 * v6;
            csum[7] += v7; csq[7] += v7 * v7;
        }
    }
    #pragma unroll
    for (int j = 0; j < 8; j++) {
        atomicAdd(&sSum[n0 + j], csum[j]);
        atomicAdd(&sSq [n0 + j], csq [j]);
    }
    __syncthreads();
    if (t < DC) {
        atomicAdd(&g_stats[t],      sSum[t]);
        atomicAdd(&g_stats[DC + t], sSq[t]);
    }

    // ---- last-CTA-done: compute BN affine in-kernel (replaces k_bn) ----
    __threadfence();
    if (t == 0) {
        int old = atomicAdd(&g_cnt, 1);
        sLast = (old == (int)gridDim.x - 1);
    }
    __syncthreads();
    if (sLast) {
        __threadfence();                 // acquire: all CTAs' stats visible
        if (t < DC) {
            float s  = g_stats[t];
            float sq = g_stats[DC + t];
            const float inv_n = 1.f / (float)NN;
            float mu  = s * inv_n;
            float var = fmaxf(sq * inv_n - mu * mu, 0.f);
            float a = __ldg(gamma + t) * rsqrtf(var + 1e-5f);
            g_aff[t]      = a;
            g_aff[DC + t] = __ldg(beta + t) - mu * a;
            g_stats[t]      = 0.f;       // restore invariants for next GEMM/replay
            g_stats[DC + t] = 0.f;
        }
        if (t == 0) g_cnt = 0;
    }
}

// ---------------- launcher ----------------------------------------------------
extern "C" void kernel_launch(void* const* d_in, const int* in_sizes, int n_in,
                              void* d_out, int out_size)
{
    const float* x   = (const float*)d_in[0];
    const int*   ei  = (const int*)  d_in[1];
    const float* W1  = (const float*)d_in[4];
    const float* b1  = (const float*)d_in[5];
    const float* g1  = (const float*)d_in[6];
    const float* be1 = (const float*)d_in[7];
    const float* W2  = (const float*)d_in[8];
    const float* b2  = (const float*)d_in[9];
    const float* g2  = (const float*)d_in[10];
    const float* be2 = (const float*)d_in[11];
    float* out = (float*)d_out;

    float *zp, *t1p, *t2p;
    cudaGetSymbolAddress((void**)&zp,  g_z);
    cudaGetSymbolAddress((void**)&t1p, g_t1);
    cudaGetSymbolAddress((void**)&t2p, g_t2);

    const size_t SMEM = (size_t)(128 * SAP + KCH * 128 + 2 * DC) * sizeof(float);
    cudaFuncSetAttribute(k_gemm<false>, cudaFuncAttributeMaxDynamicSharedMemorySize, (int)SMEM);
    cudaFuncSetAttribute(k_gemm<true>,  cudaFuncAttributeMaxDynamicSharedMemorySize, (int)SMEM);

    const int AFF_BLOCKS  = (NN * DC / 4 + 255) / 256;
    const int E4_BLOCKS   = (NE / 4 + 255) / 256;
    const int N_BLOCKS    = (NN + 255) / 256;
    const int AGG_BLOCKS  = (NN * 32 + 255) / 256;
    const int GEMM_BLOCKS = (NN + 127) / 128;

    // CSR build (every launch; deterministic)
    k_zero_deg<<<N_BLOCKS, 256>>>();
    k_hist<<<E4_BLOCKS, 256>>>(ei);
    k_scan1<<<NBLK, 1024>>>();
    k_scan2<<<1, 128>>>();
    k_scan3<<<NBLK, 1024>>>();
    k_fill<<<E4_BLOCKS, 256>>>(ei);

    const float* h = x;
    for (int l = 0; l < NL; l++) {
        if (l == 0)
            k_aggr<false><<<AGG_BLOCKS, 256>>>(h, 0);
        else
            k_aggr<true><<<AGG_BLOCKS, 256>>>(h, 1);   // prev BN2+ReLU fused
        k_gemm<false><<<GEMM_BLOCKS, 256, SMEM>>>(
            zp, W1 + l * DC * DC, b1 + l * DC, t1p, NN, g1 + l * DC, be1 + l * DC);
        k_gemm<true><<<GEMM_BLOCKS, 256, SMEM>>>(
            t1p, W2 + l * DC * DC, b2 + l * DC, t2p, NN, g2 + l * DC, be2 + l * DC);
        h = t2p;
    }
    k_affine<<<AFF_BLOCKS, 256>>>(t2p, out);   // final BN2, no ReLU
}